// round 16
// baseline (speedup 1.0000x reference)
#include <cuda_runtime.h>
#include <cstdint>

// Problem constants (fixed by setup_inputs: N=64, T=400, D=1024, M=256)
#define NTOK 25600
#define DDIM 1024
#define MCOD 256
#define ROWS_PER_BLK 64
#define KC 16
#define XLD 68        // padded row stride for xs tile (bank-conflict mitigation)
#define NCHUNK (DDIM / KC)   // 64

// ---------------- device scratch (allocation-free per harness rules) ----------------
__device__ float  g_enorm[MCOD * DDIM];
__device__ float  g_se[MCOD];
__device__ int    g_counts[MCOD];
__device__ double g_loss;

// ---------------------------------------------------------------------------
// emb_norm[m] = emb[m] / (||emb[m]|| + 1e-4);  se[m] = sum(emb_norm[m]^2)
// Replicates reference rounding: fp32 sum -> sqrtf (IEEE) -> +1e-4 -> IEEE div
// Block 0 additionally zeroes the cross-launch accumulators (graph replays).
// ---------------------------------------------------------------------------
__global__ __launch_bounds__(256) void vq_normalize(const float* __restrict__ emb) {
    __shared__ float red[256];
    const int m = blockIdx.x;
    const int t = threadIdx.x;

    if (m == 0) {
        g_counts[t] = 0;
        if (t == 0) g_loss = 0.0;
    }

    float4 v = ((const float4*)(emb + (size_t)m * DDIM))[t];
    red[t] = v.x * v.x + v.y * v.y + v.z * v.z + v.w * v.w;
    __syncthreads();
    for (int s = 128; s > 0; s >>= 1) {
        if (t < s) red[t] += red[t + s];
        __syncthreads();
    }
    float denom = __fadd_rn(sqrtf(red[0]), 1e-4f);
    __syncthreads();

    float4 e;
    e.x = __fdiv_rn(v.x, denom);
    e.y = __fdiv_rn(v.y, denom);
    e.z = __fdiv_rn(v.z, denom);
    e.w = __fdiv_rn(v.w, denom);
    ((float4*)(g_enorm + (size_t)m * DDIM))[t] = e;

    red[t] = e.x * e.x + e.y * e.y + e.z * e.z + e.w * e.w;
    __syncthreads();
    for (int s = 128; s > 0; s >>= 1) {
        if (t < s) red[t] += red[t + s];
        __syncthreads();
    }
    if (t == 0) g_se[m] = red[0];
}

// ---------------------------------------------------------------------------
// Fused main kernel (round-12 math, double-buffered tiles, ONE barrier per
// chunk): distances GEMM (64 rows x 256 codes, scalar FFMA) + argmin
// (reference fp32 rounding + lowest-index tiebreak) + gather + ST output +
// commitment loss partial + code counts.
// Pipeline per chunk c: prefetch c+1 (global->regs) -> FMA over buf[p] ->
// store regs->buf[p^1] -> __syncthreads().  Stores hit the inactive buffer,
// so one barrier suffices and LDG latency hides under the FMA section.
// sxp is accumulated in ascending-chunk order (prologue = chunk 0) ->
// bitwise-identical distances/output to round 12.
// ---------------------------------------------------------------------------
__global__ __launch_bounds__(256, 2) void vq_main(const float* __restrict__ x,
                                                  const float* __restrict__ emb,
                                                  float* __restrict__ out) {
    __shared__ __align__(16) float xs[2][KC][XLD];    // 8.7 KB
    __shared__ __align__(16) float es[2][KC][MCOD];   // 32 KB
    __shared__ float ssx[ROWS_PER_BLK];
    __shared__ int   sidx[ROWS_PER_BLK];
    __shared__ float sred[256];

    const int t   = threadIdx.x;
    const int ty  = t >> 4;
    const int tx2 = t & 15;
    const size_t rowBase = (size_t)blockIdx.x * ROWS_PER_BLK;

    float acc[4][16];
#pragma unroll
    for (int i = 0; i < 4; i++)
#pragma unroll
        for (int j = 0; j < 16; j++) acc[i][j] = 0.f;

    const int lr = t >> 2;
    const int lq = t & 3;
    const float* xld = x + (rowBase + lr) * DDIM + lq * 4;
    const float* eld = g_enorm + (size_t)t * DDIM;
    float sxp = 0.f;

    // ---- prologue: chunk 0 -> buffer 0
    {
        float4 xv = *(const float4*)(xld);
        sxp = __fmaf_rn(xv.x, xv.x, sxp);
        sxp = __fmaf_rn(xv.y, xv.y, sxp);
        sxp = __fmaf_rn(xv.z, xv.z, sxp);
        sxp = __fmaf_rn(xv.w, xv.w, sxp);
        xs[0][lq * 4 + 0][lr] = xv.x;
        xs[0][lq * 4 + 1][lr] = xv.y;
        xs[0][lq * 4 + 2][lr] = xv.z;
        xs[0][lq * 4 + 3][lr] = xv.w;
#pragma unroll
        for (int q = 0; q < 4; q++) {
            float4 ev = *(const float4*)(eld + q * 4);
            es[0][q * 4 + 0][t] = ev.x;
            es[0][q * 4 + 1][t] = ev.y;
            es[0][q * 4 + 2][t] = ev.z;
            es[0][q * 4 + 3][t] = ev.w;
        }
    }
    __syncthreads();

    // ---- main pipeline: one barrier per chunk
    int p = 0;
    for (int c = 0; c < NCHUNK; c++, p ^= 1) {
        const bool pre = (c + 1 < NCHUNK);
        float4 xv;
        float4 ev0, ev1, ev2, ev3;
        if (pre) {                       // prefetch chunk c+1 into registers
            const int kn = (c + 1) * KC;
            xv  = *(const float4*)(xld + kn);
            ev0 = *(const float4*)(eld + kn);
            ev1 = *(const float4*)(eld + kn + 4);
            ev2 = *(const float4*)(eld + kn + 8);
            ev3 = *(const float4*)(eld + kn + 12);
        }

#pragma unroll
        for (int k = 0; k < KC; k++) {
            float4 xr4 = *(const float4*)&xs[p][k][ty * 4];
            float xr[4] = {xr4.x, xr4.y, xr4.z, xr4.w};
#pragma unroll
            for (int g = 0; g < 4; g++) {
                float4 er4 = *(const float4*)&es[p][k][g * 64 + tx2 * 4];
                float er[4] = {er4.x, er4.y, er4.z, er4.w};
#pragma unroll
                for (int i = 0; i < 4; i++)
#pragma unroll
                    for (int j = 0; j < 4; j++)
                        acc[i][g * 4 + j] = __fmaf_rn(xr[i], er[j], acc[i][g * 4 + j]);
            }
        }

        if (pre) {                       // store prefetched chunk to other buffer
            sxp = __fmaf_rn(xv.x, xv.x, sxp);
            sxp = __fmaf_rn(xv.y, xv.y, sxp);
            sxp = __fmaf_rn(xv.z, xv.z, sxp);
            sxp = __fmaf_rn(xv.w, xv.w, sxp);
            const int b = p ^ 1;
            xs[b][lq * 4 + 0][lr] = xv.x;
            xs[b][lq * 4 + 1][lr] = xv.y;
            xs[b][lq * 4 + 2][lr] = xv.z;
            xs[b][lq * 4 + 3][lr] = xv.w;
            es[b][0][t]  = ev0.x;  es[b][1][t]  = ev0.y;
            es[b][2][t]  = ev0.z;  es[b][3][t]  = ev0.w;
            es[b][4][t]  = ev1.x;  es[b][5][t]  = ev1.y;
            es[b][6][t]  = ev1.z;  es[b][7][t]  = ev1.w;
            es[b][8][t]  = ev2.x;  es[b][9][t]  = ev2.y;
            es[b][10][t] = ev2.z;  es[b][11][t] = ev2.w;
            es[b][12][t] = ev3.x;  es[b][13][t] = ev3.y;
            es[b][14][t] = ev3.z;  es[b][15][t] = ev3.w;
        }
        __syncthreads();
    }

    // Combine the 4 quad-partials of sum(x^2) for row lr (lanes t&~3 .. t|3).
    sxp += __shfl_xor_sync(0xffffffffu, sxp, 1);
    sxp += __shfl_xor_sync(0xffffffffu, sxp, 2);
    if (lq == 0) ssx[lr] = sxp;
    __syncthreads();

    const float sx[4] = {ssx[ty * 4 + 0], ssx[ty * 4 + 1],
                         ssx[ty * 4 + 2], ssx[ty * 4 + 3]};

    // Per-thread argmin over its 16 codes using reference rounding:
    //   d = fl( fl(se + sx) - fl(2*dot) ), lowest index wins ties.
    float bestD[4] = {3.4e38f, 3.4e38f, 3.4e38f, 3.4e38f};
    int   bestI[4] = {0, 0, 0, 0};
#pragma unroll
    for (int g = 0; g < 4; g++) {
#pragma unroll
        for (int j = 0; j < 4; j++) {
            const int cod = g * 64 + tx2 * 4 + j;
            const float sev = g_se[cod];
#pragma unroll
            for (int i = 0; i < 4; i++) {
                float d = __fsub_rn(__fadd_rn(sev, sx[i]),
                                    __fmul_rn(2.0f, acc[i][g * 4 + j]));
                if (d < bestD[i] || (d == bestD[i] && cod < bestI[i])) {
                    bestD[i] = d;
                    bestI[i] = cod;
                }
            }
        }
    }

    // Reduce across the 16 tx2 lanes (contiguous half-warp segments).
#pragma unroll
    for (int i = 0; i < 4; i++) {
        float d = bestD[i];
        int   bi = bestI[i];
        for (int off = 8; off > 0; off >>= 1) {
            float od = __shfl_down_sync(0xffffffffu, d, off, 16);
            int   oi = __shfl_down_sync(0xffffffffu, bi, off, 16);
            if (od < d || (od == d && oi < bi)) { d = od; bi = oi; }
        }
        if (tx2 == 0) sidx[ty * 4 + i] = bi;
    }
    __syncthreads();

    if (t < ROWS_PER_BLK) atomicAdd(&g_counts[sidx[t]], 1);

    // Gather + straight-through output + loss.
    // quantized_ = fl( fl( fl(x + fl(q-x)) + q ) * 0.5 )  (exactly as reference)
    float lloss = 0.f;
    for (int r = 0; r < ROWS_PER_BLK; ++r) {
        const int idx = sidx[r];
        float4 q  = ((const float4*)(emb + (size_t)idx * DDIM))[t];
        float4 xv = ((const float4*)(x + (rowBase + r) * DDIM))[t];
        float4 o;
        {
            float st = __fadd_rn(xv.x, __fsub_rn(q.x, xv.x));
            o.x = __fmul_rn(__fadd_rn(st, q.x), 0.5f);
            float dd = __fsub_rn(xv.x, q.x);
            lloss = __fmaf_rn(dd, dd, lloss);
        }
        {
            float st = __fadd_rn(xv.y, __fsub_rn(q.y, xv.y));
            o.y = __fmul_rn(__fadd_rn(st, q.y), 0.5f);
            float dd = __fsub_rn(xv.y, q.y);
            lloss = __fmaf_rn(dd, dd, lloss);
        }
        {
            float st = __fadd_rn(xv.z, __fsub_rn(q.z, xv.z));
            o.z = __fmul_rn(__fadd_rn(st, q.z), 0.5f);
            float dd = __fsub_rn(xv.z, q.z);
            lloss = __fmaf_rn(dd, dd, lloss);
        }
        {
            float st = __fadd_rn(xv.w, __fsub_rn(q.w, xv.w));
            o.w = __fmul_rn(__fadd_rn(st, q.w), 0.5f);
            float dd = __fsub_rn(xv.w, q.w);
            lloss = __fmaf_rn(dd, dd, lloss);
        }
        ((float4*)out)[(rowBase + r) * (DDIM / 4) + t] = o;
    }

    sred[t] = lloss;
    __syncthreads();
    for (int s = 128; s > 0; s >>= 1) {
        if (t < s) sred[t] += sred[t + s];
        __syncthreads();
    }
    if (t == 0) atomicAdd(&g_loss, (double)sred[0]);
}

// ---------------------------------------------------------------------------
// Scalars: commitment_loss = mean((x-q)^2), perplexity = exp(-sum p log(p+1e-10))
// ---------------------------------------------------------------------------
__global__ void vq_finalize(float* __restrict__ out) {
    __shared__ float red[256];
    const int t = threadIdx.x;
    float p = (float)g_counts[t] / 25600.0f;
    float term = __fmul_rn(p, logf(__fadd_rn(p, 1e-10f)));
    red[t] = term;
    __syncthreads();
    for (int s = 128; s > 0; s >>= 1) {
        if (t < s) red[t] += red[t + s];
        __syncthreads();
    }
    if (t == 0) {
        out[26214400] = (float)(g_loss / 26214400.0);
        out[26214401] = expf(-red[0]);
    }
}

extern "C" void kernel_launch(void* const* d_in, const int* in_sizes, int n_in,
                              void* d_out, int out_size) {
    const float* x   = (const float*)d_in[0];
    const float* emb = (const float*)d_in[1];
    float* out = (float*)d_out;

    vq_normalize<<<MCOD, 256>>>(emb);
    vq_main<<<NTOK / ROWS_PER_BLK, 256>>>(x, emb, out);
    vq_finalize<<<1, 256>>>(out);
}

// round 17
// speedup vs baseline: 1.1057x; 1.1057x over previous
#include <cuda_runtime.h>
#include <cstdint>

// Problem constants (fixed by setup_inputs: N=64, T=400, D=1024, M=256)
#define NTOK 25600
#define DDIM 1024
#define MCOD 256
#define ROWS_PER_BLK 64
#define KC 32         // k-steps per smem tile (2x round-12; half the barriers)
#define XLD 68        // padded row stride for xs tile (bank-conflict mitigation)

// ---------------- device scratch (allocation-free per harness rules) ----------------
__device__ float  g_enorm[MCOD * DDIM];
__device__ float  g_se[MCOD];
__device__ int    g_counts[MCOD];
__device__ double g_loss;

// ---------------------------------------------------------------------------
// emb_norm[m] = emb[m] / (||emb[m]|| + 1e-4);  se[m] = sum(emb_norm[m]^2)
// Replicates reference rounding: fp32 sum -> sqrtf (IEEE) -> +1e-4 -> IEEE div
// Block 0 additionally zeroes the cross-launch accumulators (graph replays).
// ---------------------------------------------------------------------------
__global__ __launch_bounds__(256) void vq_normalize(const float* __restrict__ emb) {
    __shared__ float red[256];
    const int m = blockIdx.x;
    const int t = threadIdx.x;

    if (m == 0) {
        g_counts[t] = 0;
        if (t == 0) g_loss = 0.0;
    }

    float4 v = ((const float4*)(emb + (size_t)m * DDIM))[t];
    red[t] = v.x * v.x + v.y * v.y + v.z * v.z + v.w * v.w;
    __syncthreads();
    for (int s = 128; s > 0; s >>= 1) {
        if (t < s) red[t] += red[t + s];
        __syncthreads();
    }
    float denom = __fadd_rn(sqrtf(red[0]), 1e-4f);
    __syncthreads();

    float4 e;
    e.x = __fdiv_rn(v.x, denom);
    e.y = __fdiv_rn(v.y, denom);
    e.z = __fdiv_rn(v.z, denom);
    e.w = __fdiv_rn(v.w, denom);
    ((float4*)(g_enorm + (size_t)m * DDIM))[t] = e;

    red[t] = e.x * e.x + e.y * e.y + e.z * e.z + e.w * e.w;
    __syncthreads();
    for (int s = 128; s > 0; s >>= 1) {
        if (t < s) red[t] += red[t + s];
        __syncthreads();
    }
    if (t == 0) g_se[m] = red[0];
}

// ---------------------------------------------------------------------------
// Fused main kernel = round-12 structure with KC=32 (half the barriers).
// All per-thread access/accumulation orders are IDENTICAL to round 12:
//  - x quads: k0+lq*4 then k0+16+lq*4 (same quads, same sxp element order)
//  - e quads: q=0..7 ascending (same element order as two round-12 chunks)
//  - FMA loop: k=0..31 ascending (= two round-12 chunk bodies back-to-back)
// -> distances / argmin / output bitwise identical to round 12.
// ---------------------------------------------------------------------------
__global__ __launch_bounds__(256, 2) void vq_main(const float* __restrict__ x,
                                                  const float* __restrict__ emb,
                                                  float* __restrict__ out) {
    __shared__ __align__(16) float xs[KC][XLD];    // 8.7 KB
    __shared__ __align__(16) float es[KC][MCOD];   // 32 KB
    __shared__ float ssx[ROWS_PER_BLK];
    __shared__ int   sidx[ROWS_PER_BLK];
    __shared__ float sred[256];

    const int t   = threadIdx.x;
    const int ty  = t >> 4;
    const int tx2 = t & 15;
    const size_t rowBase = (size_t)blockIdx.x * ROWS_PER_BLK;

    float acc[4][16];
#pragma unroll
    for (int i = 0; i < 4; i++)
#pragma unroll
        for (int j = 0; j < 16; j++) acc[i][j] = 0.f;

    const int lr = t >> 2;
    const int lq = t & 3;
    const float* xld = x + (rowBase + lr) * DDIM + lq * 4;
    const float* eld = g_enorm + (size_t)t * DDIM;
    float sxp = 0.f;

    for (int k0 = 0; k0 < DDIM; k0 += KC) {
        // x tile: two quads per thread, same positions/order as round 12
        {
            float4 xv = *(const float4*)(xld + k0);
            sxp = __fmaf_rn(xv.x, xv.x, sxp);
            sxp = __fmaf_rn(xv.y, xv.y, sxp);
            sxp = __fmaf_rn(xv.z, xv.z, sxp);
            sxp = __fmaf_rn(xv.w, xv.w, sxp);
            xs[lq * 4 + 0][lr] = xv.x;
            xs[lq * 4 + 1][lr] = xv.y;
            xs[lq * 4 + 2][lr] = xv.z;
            xs[lq * 4 + 3][lr] = xv.w;
            float4 xw = *(const float4*)(xld + k0 + 16);
            sxp = __fmaf_rn(xw.x, xw.x, sxp);
            sxp = __fmaf_rn(xw.y, xw.y, sxp);
            sxp = __fmaf_rn(xw.z, xw.z, sxp);
            sxp = __fmaf_rn(xw.w, xw.w, sxp);
            xs[16 + lq * 4 + 0][lr] = xw.x;
            xs[16 + lq * 4 + 1][lr] = xw.y;
            xs[16 + lq * 4 + 2][lr] = xw.z;
            xs[16 + lq * 4 + 3][lr] = xw.w;
        }
        // e tile: 8 ascending quads for code t
#pragma unroll
        for (int q = 0; q < 8; q++) {
            float4 ev = *(const float4*)(eld + k0 + q * 4);
            es[q * 4 + 0][t] = ev.x;
            es[q * 4 + 1][t] = ev.y;
            es[q * 4 + 2][t] = ev.z;
            es[q * 4 + 3][t] = ev.w;
        }
        __syncthreads();

#pragma unroll
        for (int k = 0; k < KC; k++) {
            float4 xr4 = *(const float4*)&xs[k][ty * 4];
            float xr[4] = {xr4.x, xr4.y, xr4.z, xr4.w};
#pragma unroll
            for (int g = 0; g < 4; g++) {
                float4 er4 = *(const float4*)&es[k][g * 64 + tx2 * 4];
                float er[4] = {er4.x, er4.y, er4.z, er4.w};
#pragma unroll
                for (int i = 0; i < 4; i++)
#pragma unroll
                    for (int j = 0; j < 4; j++)
                        acc[i][g * 4 + j] = __fmaf_rn(xr[i], er[j], acc[i][g * 4 + j]);
            }
        }
        __syncthreads();
    }

    // Combine the 4 quad-partials of sum(x^2) for row lr (lanes t&~3 .. t|3).
    sxp += __shfl_xor_sync(0xffffffffu, sxp, 1);
    sxp += __shfl_xor_sync(0xffffffffu, sxp, 2);
    if (lq == 0) ssx[lr] = sxp;
    __syncthreads();

    const float sx[4] = {ssx[ty * 4 + 0], ssx[ty * 4 + 1],
                         ssx[ty * 4 + 2], ssx[ty * 4 + 3]};

    // Per-thread argmin over its 16 codes using reference rounding:
    //   d = fl( fl(se + sx) - fl(2*dot) ), lowest index wins ties.
    float bestD[4] = {3.4e38f, 3.4e38f, 3.4e38f, 3.4e38f};
    int   bestI[4] = {0, 0, 0, 0};
#pragma unroll
    for (int g = 0; g < 4; g++) {
#pragma unroll
        for (int j = 0; j < 4; j++) {
            const int cod = g * 64 + tx2 * 4 + j;
            const float sev = g_se[cod];
#pragma unroll
            for (int i = 0; i < 4; i++) {
                float d = __fsub_rn(__fadd_rn(sev, sx[i]),
                                    __fmul_rn(2.0f, acc[i][g * 4 + j]));
                if (d < bestD[i] || (d == bestD[i] && cod < bestI[i])) {
                    bestD[i] = d;
                    bestI[i] = cod;
                }
            }
        }
    }

    // Reduce across the 16 tx2 lanes (contiguous half-warp segments).
#pragma unroll
    for (int i = 0; i < 4; i++) {
        float d = bestD[i];
        int   bi = bestI[i];
        for (int off = 8; off > 0; off >>= 1) {
            float od = __shfl_down_sync(0xffffffffu, d, off, 16);
            int   oi = __shfl_down_sync(0xffffffffu, bi, off, 16);
            if (od < d || (od == d && oi < bi)) { d = od; bi = oi; }
        }
        if (tx2 == 0) sidx[ty * 4 + i] = bi;
    }
    __syncthreads();

    if (t < ROWS_PER_BLK) atomicAdd(&g_counts[sidx[t]], 1);

    // Gather + straight-through output + loss.
    // quantized_ = fl( fl( fl(x + fl(q-x)) + q ) * 0.5 )  (exactly as reference)
    float lloss = 0.f;
    for (int r = 0; r < ROWS_PER_BLK; ++r) {
        const int idx = sidx[r];
        float4 q  = ((const float4*)(emb + (size_t)idx * DDIM))[t];
        float4 xv = ((const float4*)(x + (rowBase + r) * DDIM))[t];
        float4 o;
        {
            float st = __fadd_rn(xv.x, __fsub_rn(q.x, xv.x));
            o.x = __fmul_rn(__fadd_rn(st, q.x), 0.5f);
            float dd = __fsub_rn(xv.x, q.x);
            lloss = __fmaf_rn(dd, dd, lloss);
        }
        {
            float st = __fadd_rn(xv.y, __fsub_rn(q.y, xv.y));
            o.y = __fmul_rn(__fadd_rn(st, q.y), 0.5f);
            float dd = __fsub_rn(xv.y, q.y);
            lloss = __fmaf_rn(dd, dd, lloss);
        }
        {
            float st = __fadd_rn(xv.z, __fsub_rn(q.z, xv.z));
            o.z = __fmul_rn(__fadd_rn(st, q.z), 0.5f);
            float dd = __fsub_rn(xv.z, q.z);
            lloss = __fmaf_rn(dd, dd, lloss);
        }
        {
            float st = __fadd_rn(xv.w, __fsub_rn(q.w, xv.w));
            o.w = __fmul_rn(__fadd_rn(st, q.w), 0.5f);
            float dd = __fsub_rn(xv.w, q.w);
            lloss = __fmaf_rn(dd, dd, lloss);
        }
        ((float4*)out)[(rowBase + r) * (DDIM / 4) + t] = o;
    }

    sred[t] = lloss;
    __syncthreads();
    for (int s = 128; s > 0; s >>= 1) {
        if (t < s) sred[t] += sred[t + s];
        __syncthreads();
    }
    if (t == 0) atomicAdd(&g_loss, (double)sred[0]);
}

// ---------------------------------------------------------------------------
// Scalars: commitment_loss = mean((x-q)^2), perplexity = exp(-sum p log(p+1e-10))
// ---------------------------------------------------------------------------
__global__ void vq_finalize(float* __restrict__ out) {
    __shared__ float red[256];
    const int t = threadIdx.x;
    float p = (float)g_counts[t] / 25600.0f;
    float term = __fmul_rn(p, logf(__fadd_rn(p, 1e-10f)));
    red[t] = term;
    __syncthreads();
    for (int s = 128; s > 0; s >>= 1) {
        if (t < s) red[t] += red[t + s];
        __syncthreads();
    }
    if (t == 0) {
        out[26214400] = (float)(g_loss / 26214400.0);
        out[26214401] = expf(-red[0]);
    }
}

extern "C" void kernel_launch(void* const* d_in, const int* in_sizes, int n_in,
                              void* d_out, int out_size) {
    const float* x   = (const float*)d_in[0];
    const float* emb = (const float*)d_in[1];
    float* out = (float*)d_out;

    vq_normalize<<<MCOD, 256>>>(emb);
    vq_main<<<NTOK / ROWS_PER_BLK, 256>>>(x, emb, out);
    vq_finalize<<<1, 256>>>(out);
}